// round 12
// baseline (speedup 1.0000x reference)
#include <cuda_runtime.h>
#include <cuda_bf16.h>
#include <stdint.h>

// m=n=8192, k=64 fixed. Output dtype: float32 (quantized integer values).
#define COLS   8192
#define KDIM   64
#define GRIDN  296               // 2 persistent CTAs per SM
#define THREADS 256

// smem word offsets
#define XS_STRIDE 36                     // words per chunk (32 bf16x2 + pad)
#define XS_PLANE  (128*XS_STRIDE)        // 4608 words
#define OFF_XS    0                      // 4 planes: (buf*2 + split)*XS_PLANE
#define HS_STRIDE 72
#define HS_PLANE  (32*HS_STRIDE)         // 2304 words
#define OFF_H1    (4*XS_PLANE)           // 18432
#define OFF_H2    (OFF_H1 + HS_PLANE)
#define OFF_RED   (OFF_H2 + HS_PLANE)    // 23040 (+16 words: 2 parity x 8)
#define SMEM_WORDS (OFF_RED + 16)
#define SMEM_BYTES (SMEM_WORDS*4)        // 92224 B -> 2 CTAs/SM

#define MMA16(dd, A, B)                                                        \
    asm volatile("mma.sync.aligned.m16n8k16.row.col.f32.bf16.bf16.f32 "        \
        "{%0,%1,%2,%3}, {%4,%5,%6,%7}, {%8,%9}, {%0,%1,%2,%3};"                \
        : "+f"((dd)[0]), "+f"((dd)[1]), "+f"((dd)[2]), "+f"((dd)[3])           \
        : "r"((A)[0]), "r"((A)[1]), "r"((A)[2]), "r"((A)[3]),                  \
          "r"((B)[0]), "r"((B)[1]))

__device__ __forceinline__ void split2f(float v, float& f1, float& f2) {
    f1 = __bfloat162float(__float2bfloat16(v));
    f2 = __bfloat162float(__float2bfloat16(v - f1));
}
__device__ __forceinline__ uint32_t packbf(float lo, float hi) {
    return __byte_perm(__float_as_uint(lo), __float_as_uint(hi), 0x7632);
}

// Coalesced direct LDG of one row: thread t owns float4 at p*1024 + t*4.
__device__ __forceinline__ void row_ldg(const float* __restrict__ src, int t, float4 raw[8]) {
    #pragma unroll
    for (int p = 0; p < 8; ++p)
        raw[p] = *(const float4*)(src + p * 1024 + t * 4);
}

// Convert + store to planes[buf]: chunk c = p*16 + (t>>4), word offset (t&15)*2.
__device__ __forceinline__ void row_sts(uint32_t* sm, int buf, int t, const float4 raw[8]) {
    const int cL = t >> 4;
    const int ip = (t & 15) * 2;
    uint32_t* p1 = sm + OFF_XS + (buf * 2 + 0) * XS_PLANE + ip;
    uint32_t* p2 = sm + OFF_XS + (buf * 2 + 1) * XS_PLANE + ip;
    #pragma unroll
    for (int p = 0; p < 8; ++p) {
        float a1, a2, b1, b2, c1, c2, e1, e2;
        split2f(raw[p].x, a1, a2); split2f(raw[p].y, b1, b2);
        split2f(raw[p].z, c1, c2); split2f(raw[p].w, e1, e2);
        const int c = p * 16 + cL;
        *(uint2*)(p1 + c * XS_STRIDE) = make_uint2(packbf(a1, b1), packbf(c1, e1));
        *(uint2*)(p2 + c * XS_STRIDE) = make_uint2(packbf(a2, b2), packbf(c2, e2));
    }
}

__global__ __launch_bounds__(THREADS, 2)
void bdq10_kernel(const float* __restrict__ x, const float* __restrict__ hmat,
                  float* __restrict__ out, int nrows)
{
    extern __shared__ uint32_t sm[];
    const int t  = threadIdx.x;
    const int w  = t >> 5, L = t & 31;
    const int g  = L >> 2, tq = L & 3;       // quad layout
    const int mw = w & 3,  nw = w >> 2;      // warp tile: 32 chunks x 32 cols

    // ---- h -> 2 bf16x2 planes ----
    {
        const int j = t & 63;
        const int kp0 = (t >> 6) * 8;
        #pragma unroll
        for (int p = 0; p < 8; ++p) {
            const int kp = kp0 + p;
            const float ve = hmat[(2 * kp)     * 64 + j];
            const float vo = hmat[(2 * kp + 1) * 64 + j];
            float e1, e2, o1, o2;
            split2f(ve, e1, e2); split2f(vo, o1, o2);
            sm[OFF_H1 + kp * HS_STRIDE + j] = packbf(e1, o1);
            sm[OFF_H2 + kp * HS_STRIDE + j] = packbf(e2, o2);
        }
    }

    // ---- first row -> planes buf 0 ----
    long row = blockIdx.x;
    {
        float4 raw[8];
        row_ldg(x + row * (long)COLS, t, raw);
        row_sts(sm, 0, t, raw);
    }
    __syncthreads();

    // ---- register-resident h1 B-fragments (row-invariant) ----
    uint32_t Bh1[4][4][2];
    #pragma unroll
    for (int kt = 0; kt < 4; ++kt)
        #pragma unroll
        for (int nt = 0; nt < 4; ++nt) {
            const uint32_t* pb = sm + OFF_H1 + (kt * 8 + tq) * HS_STRIDE + nw * 32 + nt * 8 + g;
            Bh1[kt][nt][0] = pb[0];
            Bh1[kt][nt][1] = pb[4 * HS_STRIDE];
        }

    int buf = 0, parity = 0;
    for (; row < nrows; row += GRIDN) {
        // ===== MMA(row): 4 kt x 4 nt x 2 mf x 4 products, planes[buf] =====
        float d[2][4][4];
        #pragma unroll
        for (int mf = 0; mf < 2; ++mf)
            #pragma unroll
            for (int nt = 0; nt < 4; ++nt)
                #pragma unroll
                for (int e = 0; e < 4; ++e) d[mf][nt][e] = 0.0f;

        const uint32_t* xs1 = sm + OFF_XS + (buf * 2 + 0) * XS_PLANE;
        const uint32_t* xs2 = sm + OFF_XS + (buf * 2 + 1) * XS_PLANE;

        #pragma unroll
        for (int kt = 0; kt < 4; ++kt) {
            uint32_t A1[2][4], A2[2][4];
            #pragma unroll
            for (int mf = 0; mf < 2; ++mf) {
                const int co = (mw * 32 + mf * 16 + g) * XS_STRIDE + kt * 8 + tq;
                A1[mf][0] = xs1[co];
                A1[mf][1] = xs1[co + 8 * XS_STRIDE];
                A1[mf][2] = xs1[co + 4];
                A1[mf][3] = xs1[co + 8 * XS_STRIDE + 4];
                A2[mf][0] = xs2[co];
                A2[mf][1] = xs2[co + 8 * XS_STRIDE];
                A2[mf][2] = xs2[co + 4];
                A2[mf][3] = xs2[co + 8 * XS_STRIDE + 4];
            }
            #pragma unroll
            for (int nt = 0; nt < 4; ++nt) {
                const uint32_t* pb = sm + OFF_H2 + (kt * 8 + tq) * HS_STRIDE + nw * 32 + nt * 8 + g;
                uint32_t B2[2];
                B2[0] = pb[0];
                B2[1] = pb[4 * HS_STRIDE];
                #pragma unroll
                for (int mf = 0; mf < 2; ++mf) {
                    MMA16(d[mf][nt], A1[mf], Bh1[kt][nt]);   // x1*h1
                    MMA16(d[mf][nt], A1[mf], B2);            // x1*h2
                    MMA16(d[mf][nt], A2[mf], Bh1[kt][nt]);   // x2*h1
                    MMA16(d[mf][nt], A2[mf], B2);            // x2*h2
                }
            }
        }

        // ---- issue next row's LDGs immediately (latency hidden by reduce) ----
        const long nxt = row + GRIDN;
        float4 raw[8];
        if (nxt < nrows) row_ldg(x + nxt * (long)COLS, t, raw);

        // ---- row absmax (overlaps LDG latency) ----
        float m = 0.0f;
        #pragma unroll
        for (int mf = 0; mf < 2; ++mf)
            #pragma unroll
            for (int nt = 0; nt < 4; ++nt)
                #pragma unroll
                for (int e = 0; e < 4; ++e)
                    m = fmaxf(m, fabsf(d[mf][nt][e]));
        #pragma unroll
        for (int o = 16; o > 0; o >>= 1)
            m = fmaxf(m, __shfl_xor_sync(0xffffffffu, m, o));
        float* redf = (float*)(sm + OFF_RED) + parity * 8;
        if (L == 0) redf[w] = m;

        // ---- convert + store next row into planes[buf^1] ----
        if (nxt < nrows) row_sts(sm, buf ^ 1, t, raw);

        __syncthreads();   // publishes planes[buf^1] AND redf[parity]

        // ---- scale + quantize (round-half-even) + store float32 ----
        float a = redf[0];
        #pragma unroll
        for (int ww = 1; ww < 8; ++ww) a = fmaxf(a, redf[ww]);
        const float inv = (a == 0.0f) ? 0.0f : __fdiv_rn(127.0f, a);

        float* orow = out + row * (long)COLS;
        #pragma unroll
        for (int mf = 0; mf < 2; ++mf) {
            const int c0 = mw * 32 + mf * 16 + g;
            #pragma unroll
            for (int nt = 0; nt < 4; ++nt) {
                const int j0 = nw * 32 + nt * 8 + tq * 2;
                float q0 = fminf(fmaxf(rintf(d[mf][nt][0] * inv), -128.0f), 127.0f);
                float q1 = fminf(fmaxf(rintf(d[mf][nt][1] * inv), -128.0f), 127.0f);
                float q2 = fminf(fmaxf(rintf(d[mf][nt][2] * inv), -128.0f), 127.0f);
                float q3 = fminf(fmaxf(rintf(d[mf][nt][3] * inv), -128.0f), 127.0f);
                *(float2*)(orow + c0 * 64 + j0)       = make_float2(q0, q1);
                *(float2*)(orow + (c0 + 8) * 64 + j0) = make_float2(q2, q3);
            }
        }

        buf ^= 1;
        parity ^= 1;
    }
}

extern "C" void kernel_launch(void* const* d_in, const int* in_sizes, int n_in,
                              void* d_out, int out_size)
{
    const float* x;
    const float* h;
    long x_elems;
    if (in_sizes[0] > in_sizes[1]) {
        x = (const float*)d_in[0]; h = (const float*)d_in[1]; x_elems = in_sizes[0];
    } else {
        x = (const float*)d_in[1]; h = (const float*)d_in[0]; x_elems = in_sizes[1];
    }
    const int nrows = (int)(x_elems / COLS);

    cudaFuncSetAttribute(bdq10_kernel, cudaFuncAttributeMaxDynamicSharedMemorySize, SMEM_BYTES);
    bdq10_kernel<<<GRIDN, THREADS, SMEM_BYTES>>>(x, h, (float*)d_out, nrows);
}